// round 4
// baseline (speedup 1.0000x reference)
#include <cuda_runtime.h>
#include <cstdint>

#define N_ATOMS 50000
#define N_PAIRS 600000
#define DB 128
#define NRBF 20

// Scratch (allocation-free rule: __device__ globals)
__device__ float g_h[(size_t)N_ATOMS * DB];    // 25.6 MB
__device__ float g_agg[(size_t)N_ATOMS * DB];  // 25.6 MB
__device__ int2  g_pairs[N_PAIRS];             // 4.8 MB (i, j) as int32
__device__ int   g_is64;                       // pairlist dtype flag

__device__ __forceinline__ float ssp(float x) {
    // softplus(x) - ln(2), overflow-safe
    return fmaxf(x, 0.f) + log1pf(__expf(-fabsf(x))) - 0.6931471805599453f;
}

__device__ __forceinline__ void red_add_v4(float* a, float4 v) {
    asm volatile("red.global.add.v4.f32 [%0], {%1,%2,%3,%4};"
                 :: "l"(a), "f"(v.x), "f"(v.y), "f"(v.z), "f"(v.w)
                 : "memory");
}

// ----------------------------------------------------------------------------
// Pairlist dtype detection + conversion to int2.
// If pairlist is int64 (values < 50000), every odd 32-bit word is 0.
// If int32, odd words are random indices -> OR over 1024 of them is nonzero
// with probability ~1. Deterministic: same input -> same flag every call.
// ----------------------------------------------------------------------------
__global__ void detect_idx_kernel(const unsigned int* __restrict__ pw) {
    __shared__ unsigned int s_or;
    if (threadIdx.x == 0) s_or = 0u;
    __syncthreads();
    unsigned int v = 0u;
    for (int i = threadIdx.x; i < 1024; i += blockDim.x)
        v |= pw[2 * i + 1];
    atomicOr(&s_or, v);
    __syncthreads();
    if (threadIdx.x == 0) g_is64 = (s_or == 0u) ? 1 : 0;
}

__global__ void convert_idx_kernel(const void* __restrict__ pl) {
    int p = blockIdx.x * blockDim.x + threadIdx.x;
    if (p >= N_PAIRS) return;
    int i, j;
    if (g_is64) {
        const long long* q = (const long long*)pl;
        i = (int)q[p];
        j = (int)q[N_PAIRS + p];
    } else {
        const int* q = (const int*)pl;
        i = q[p];
        j = q[N_PAIRS + p];
    }
    g_pairs[p] = make_int2(i, j);
}

// ----------------------------------------------------------------------------
// Zero the aggregation buffer (kernel instead of memset: keeps the captured
// graph kernel-nodes-only).
// ----------------------------------------------------------------------------
__global__ void zero_agg_kernel() {
    size_t idx = (size_t)blockIdx.x * blockDim.x + threadIdx.x;
    size_t n4 = (size_t)N_ATOMS * DB / 4;
    if (idx < n4)
        ((float4*)g_agg)[idx] = make_float4(0.f, 0.f, 0.f, 0.f);
}

// ----------------------------------------------------------------------------
// C[M,128] = A[M,128] @ W[128,128] + bias   (optional shifted-softplus epilogue)
// BM=128, BN=128, BK=16, 256 threads, 8x8 per thread.
// ----------------------------------------------------------------------------
template <bool DO_SSP>
__global__ __launch_bounds__(256) void gemm128_kernel(
    const float* __restrict__ A, const float* __restrict__ W,
    const float* __restrict__ bias, float* __restrict__ C, int M)
{
    __shared__ float As[16 * 132];  // [k][m], padded stride 132
    __shared__ float Bs[16 * 128];  // [k][n]

    const int tid = threadIdx.x;
    const int tx = tid & 15;       // n-tile 0..15
    const int ty = tid >> 4;       // m-tile 0..15
    const int m0 = blockIdx.x * 128;

    float acc[8][8];
    #pragma unroll
    for (int i = 0; i < 8; i++)
        #pragma unroll
        for (int j = 0; j < 8; j++) acc[i][j] = 0.f;

    for (int kt = 0; kt < 128; kt += 16) {
        // Load A tile (transposed into [k][m]) and B tile
        #pragma unroll
        for (int i = 0; i < 2; i++) {
            int idx = tid * 2 + i;          // 0..511
            int row = idx >> 2;             // 0..127
            int c4  = idx & 3;              // 0..3
            float4 av = make_float4(0.f, 0.f, 0.f, 0.f);
            int grow = m0 + row;
            if (grow < M)
                av = *(const float4*)&A[(size_t)grow * DB + kt + c4 * 4];
            As[(c4 * 4 + 0) * 132 + row] = av.x;
            As[(c4 * 4 + 1) * 132 + row] = av.y;
            As[(c4 * 4 + 2) * 132 + row] = av.z;
            As[(c4 * 4 + 3) * 132 + row] = av.w;

            int k = idx >> 5;               // 0..15
            int c = idx & 31;               // 0..31
            *(float4*)&Bs[k * 128 + c * 4] =
                *(const float4*)&W[(size_t)(kt + k) * DB + c * 4];
        }
        __syncthreads();

        #pragma unroll
        for (int kk = 0; kk < 16; kk++) {
            float a[8], b[8];
            *(float4*)&a[0] = *(const float4*)&As[kk * 132 + ty * 8];
            *(float4*)&a[4] = *(const float4*)&As[kk * 132 + ty * 8 + 4];
            *(float4*)&b[0] = *(const float4*)&Bs[kk * 128 + tx * 8];
            *(float4*)&b[4] = *(const float4*)&Bs[kk * 128 + tx * 8 + 4];
            #pragma unroll
            for (int i = 0; i < 8; i++)
                #pragma unroll
                for (int j = 0; j < 8; j++)
                    acc[i][j] = fmaf(a[i], b[j], acc[i][j]);
        }
        __syncthreads();
    }

    // Epilogue
    float bb[8];
    *(float4*)&bb[0] = *(const float4*)&bias[tx * 8];
    *(float4*)&bb[4] = *(const float4*)&bias[tx * 8 + 4];

    #pragma unroll
    for (int i = 0; i < 8; i++) {
        int grow = m0 + ty * 8 + i;
        if (grow >= M) continue;
        float v[8];
        #pragma unroll
        for (int j = 0; j < 8; j++) {
            float c = acc[i][j] + bb[j];
            v[j] = DO_SSP ? ssp(c) : c;
        }
        *(float4*)&C[(size_t)grow * DB + tx * 8]     = *(float4*)&v[0];
        *(float4*)&C[(size_t)grow * DB + tx * 8 + 4] = *(float4*)&v[4];
    }
}

// ----------------------------------------------------------------------------
// Edge kernel: one warp per pair.
//   Wij = (softplus(f_ij @ W_f + b_f) - ln2) * rcut_ij
//   agg[i] += h[j] * Wij      (red.global.add.v4.f32, no return trip)
// Lane l owns columns 4l..4l+3; W_f columns held in registers (80 regs/lane).
// ----------------------------------------------------------------------------
__global__ void edge_kernel(
    const float* __restrict__ f, const float* __restrict__ rcut,
    const float* __restrict__ Wf, const float* __restrict__ bf)
{
    const int lane = threadIdx.x & 31;
    const int warp = threadIdx.x >> 5;
    const int nwarps = gridDim.x * (blockDim.x >> 5);
    const int gw = blockIdx.x * (blockDim.x >> 5) + warp;

    // W_f[:, 4*lane .. 4*lane+3] in registers
    float w0[NRBF], w1[NRBF], w2[NRBF], w3[NRBF];
    #pragma unroll
    for (int k = 0; k < NRBF; k++) {
        float4 wv = *(const float4*)&Wf[k * DB + lane * 4];
        w0[k] = wv.x; w1[k] = wv.y; w2[k] = wv.z; w3[k] = wv.w;
    }
    const float4 bv = *(const float4*)&bf[lane * 4];

    for (int p = gw; p < N_PAIRS; p += nwarps) {
        float fv = (lane < NRBF) ? __ldg(&f[(size_t)p * NRBF + lane]) : 0.f;
        int2 ij = g_pairs[p];                 // broadcast load (all lanes same addr)
        float rc = __ldg(&rcut[p]);

        float a0 = bv.x, a1 = bv.y, a2 = bv.z, a3 = bv.w;
        #pragma unroll
        for (int k = 0; k < NRBF; k++) {
            float fk = __shfl_sync(0xffffffffu, fv, k);
            a0 = fmaf(fk, w0[k], a0);
            a1 = fmaf(fk, w1[k], a1);
            a2 = fmaf(fk, w2[k], a2);
            a3 = fmaf(fk, w3[k], a3);
        }
        a0 = ssp(a0) * rc;
        a1 = ssp(a1) * rc;
        a2 = ssp(a2) * rc;
        a3 = ssp(a3) * rc;

        float4 hv = *(const float4*)&g_h[(size_t)ij.y * DB + lane * 4];
        float4 v;
        v.x = hv.x * a0; v.y = hv.y * a1; v.z = hv.z * a2; v.w = hv.w * a3;
        red_add_v4(&g_agg[(size_t)ij.x * DB + lane * 4], v);
    }
}

// ----------------------------------------------------------------------------

extern "C" void kernel_launch(void* const* d_in, const int* in_sizes, int n_in,
                              void* d_out, int out_size)
{
    const float* x     = (const float*)d_in[0];
    const void*  pl    = d_in[1];
    const float* f_ij  = (const float*)d_in[2];
    const float* rcut  = (const float*)d_in[3];
    const float* W_in  = (const float*)d_in[4];
    const float* b_in  = (const float*)d_in[5];
    const float* W_f   = (const float*)d_in[6];
    const float* b_f   = (const float*)d_in[7];
    const float* W_out = (const float*)d_in[8];
    const float* b_out = (const float*)d_in[9];
    float*       out   = (float*)d_out;

    float* hbuf;  cudaGetSymbolAddress((void**)&hbuf, g_h);
    float* abuf;  cudaGetSymbolAddress((void**)&abuf, g_agg);

    const int gemm_grid = (N_ATOMS + 127) / 128;  // 391

    // 0) pairlist dtype sniff + convert to int2
    detect_idx_kernel<<<1, 256>>>((const unsigned int*)pl);
    convert_idx_kernel<<<(N_PAIRS + 255) / 256, 256>>>(pl);
    // 1) h = x @ W_in + b_in
    gemm128_kernel<false><<<gemm_grid, 256>>>(x, W_in, b_in, hbuf, N_ATOMS);
    // 2) agg = 0
    zero_agg_kernel<<<(N_ATOMS * DB / 4 + 255) / 256, 256>>>();
    // 3) edges: gather/modulate/scatter
    edge_kernel<<<1776, 256>>>(f_ij, rcut, W_f, b_f);
    // 4) out = ssp(agg @ W_out + b_out)
    gemm128_kernel<true><<<gemm_grid, 256>>>(abuf, W_out, b_out, out, N_ATOMS);
}

// round 5
// speedup vs baseline: 1.2201x; 1.2201x over previous
#include <cuda_runtime.h>
#include <cstdint>

#define N_ATOMS 50000
#define N_PAIRS 600000
#define DB 128
#define NRBF 20

// Scratch (allocation-free rule: __device__ globals)
__device__ float g_h[(size_t)N_ATOMS * DB];    // 25.6 MB
__device__ float g_agg[(size_t)N_ATOMS * DB];  // 25.6 MB
__device__ int2  g_pairs[N_PAIRS];             // 4.8 MB (i, j) as int32

// Fast shifted-softplus: softplus(x) - ln2, overflow-safe, MUFU-based.
// |abs err| ~4e-7, output tolerance is 1e-3 rel -> plenty of headroom.
__device__ __forceinline__ float ssp(float x) {
    float t = __expf(-fabsf(x));
    return fmaxf(x, 0.f) + __logf(1.f + t) - 0.6931471805599453f;
}

__device__ __forceinline__ void red_add_v4(float* a, float4 v) {
    asm volatile("red.global.add.v4.f32 [%0], {%1,%2,%3,%4};"
                 :: "l"(a), "f"(v.x), "f"(v.y), "f"(v.z), "f"(v.w)
                 : "memory");
}

// ----------------------------------------------------------------------------
// Pairlist convert to int2 with per-block dtype detection.
// int64 indices < 50000 -> every odd 32-bit word is 0. For int32 random
// indices the OR over 1024 odd words is nonzero with probability ~1.
// Each block re-derives the flag from the same fixed 1024 words
// (deterministic, no cross-kernel dependency).
// ----------------------------------------------------------------------------
__global__ void convert_idx_kernel(const void* __restrict__ pl) {
    __shared__ unsigned int s_or;
    if (threadIdx.x == 0) s_or = 0u;
    __syncthreads();
    const unsigned int* pw = (const unsigned int*)pl;
    unsigned int v = 0u;
    for (int i = threadIdx.x; i < 1024; i += blockDim.x)
        v |= pw[2 * i + 1];
    atomicOr(&s_or, v);
    __syncthreads();
    const bool is64 = (s_or == 0u);

    int p = blockIdx.x * blockDim.x + threadIdx.x;
    if (p >= N_PAIRS) return;
    int i, j;
    if (is64) {
        const long long* q = (const long long*)pl;
        i = (int)q[p];
        j = (int)q[N_PAIRS + p];
    } else {
        const int* q = (const int*)pl;
        i = q[p];
        j = q[N_PAIRS + p];
    }
    g_pairs[p] = make_int2(i, j);
}

// ----------------------------------------------------------------------------
// Zero the aggregation buffer.
// ----------------------------------------------------------------------------
__global__ void zero_agg_kernel() {
    size_t idx = (size_t)blockIdx.x * blockDim.x + threadIdx.x;
    size_t n4 = (size_t)N_ATOMS * DB / 4;
    if (idx < n4)
        ((float4*)g_agg)[idx] = make_float4(0.f, 0.f, 0.f, 0.f);
}

// ----------------------------------------------------------------------------
// C[M,128] = A[M,128] @ W[128,128] + bias   (optional shifted-softplus epilogue)
// BM=128, BN=128, BK=16, 256 threads, 8x8 per thread.
// ----------------------------------------------------------------------------
template <bool DO_SSP>
__global__ __launch_bounds__(256) void gemm128_kernel(
    const float* __restrict__ A, const float* __restrict__ W,
    const float* __restrict__ bias, float* __restrict__ C, int M)
{
    __shared__ float As[16 * 132];  // [k][m], padded stride 132
    __shared__ float Bs[16 * 128];  // [k][n]

    const int tid = threadIdx.x;
    const int tx = tid & 15;       // n-tile 0..15
    const int ty = tid >> 4;       // m-tile 0..15
    const int m0 = blockIdx.x * 128;

    float acc[8][8];
    #pragma unroll
    for (int i = 0; i < 8; i++)
        #pragma unroll
        for (int j = 0; j < 8; j++) acc[i][j] = 0.f;

    for (int kt = 0; kt < 128; kt += 16) {
        #pragma unroll
        for (int i = 0; i < 2; i++) {
            int idx = tid * 2 + i;          // 0..511
            int row = idx >> 2;             // 0..127
            int c4  = idx & 3;              // 0..3
            float4 av = make_float4(0.f, 0.f, 0.f, 0.f);
            int grow = m0 + row;
            if (grow < M)
                av = *(const float4*)&A[(size_t)grow * DB + kt + c4 * 4];
            As[(c4 * 4 + 0) * 132 + row] = av.x;
            As[(c4 * 4 + 1) * 132 + row] = av.y;
            As[(c4 * 4 + 2) * 132 + row] = av.z;
            As[(c4 * 4 + 3) * 132 + row] = av.w;

            int k = idx >> 5;               // 0..15
            int c = idx & 31;               // 0..31
            *(float4*)&Bs[k * 128 + c * 4] =
                *(const float4*)&W[(size_t)(kt + k) * DB + c * 4];
        }
        __syncthreads();

        #pragma unroll
        for (int kk = 0; kk < 16; kk++) {
            float a[8], b[8];
            *(float4*)&a[0] = *(const float4*)&As[kk * 132 + ty * 8];
            *(float4*)&a[4] = *(const float4*)&As[kk * 132 + ty * 8 + 4];
            *(float4*)&b[0] = *(const float4*)&Bs[kk * 128 + tx * 8];
            *(float4*)&b[4] = *(const float4*)&Bs[kk * 128 + tx * 8 + 4];
            #pragma unroll
            for (int i = 0; i < 8; i++)
                #pragma unroll
                for (int j = 0; j < 8; j++)
                    acc[i][j] = fmaf(a[i], b[j], acc[i][j]);
        }
        __syncthreads();
    }

    float bb[8];
    *(float4*)&bb[0] = *(const float4*)&bias[tx * 8];
    *(float4*)&bb[4] = *(const float4*)&bias[tx * 8 + 4];

    #pragma unroll
    for (int i = 0; i < 8; i++) {
        int grow = m0 + ty * 8 + i;
        if (grow >= M) continue;
        float v[8];
        #pragma unroll
        for (int j = 0; j < 8; j++) {
            float c = acc[i][j] + bb[j];
            v[j] = DO_SSP ? ssp(c) : c;
        }
        *(float4*)&C[(size_t)grow * DB + tx * 8]     = *(float4*)&v[0];
        *(float4*)&C[(size_t)grow * DB + tx * 8 + 4] = *(float4*)&v[4];
    }
}

// ----------------------------------------------------------------------------
// Edge kernel, software-pipelined: one warp per pair, grid-stride.
//   Wij = ssp(f_ij @ W_f + b_f) * rcut_ij
//   agg[i] += h[j] * Wij        (red.global.add.v4.f32)
// Lane l owns columns 4l..4l+3; W_f columns in registers (80/lane).
// Pipeline: issue h[j] gather for pair p and metadata loads for pair p+1
// BEFORE the Wij FMA chain for p, so ~110 cycles of compute hide the
// ~250-cycle L2 latencies.
// ----------------------------------------------------------------------------
__global__ __launch_bounds__(256) void edge_kernel(
    const float* __restrict__ f, const float* __restrict__ rcut,
    const float* __restrict__ Wf, const float* __restrict__ bf)
{
    const int lane = threadIdx.x & 31;
    const int warp = threadIdx.x >> 5;
    const int nwarps = gridDim.x * (blockDim.x >> 5);
    const int gw = blockIdx.x * (blockDim.x >> 5) + warp;

    // W_f[:, 4*lane .. 4*lane+3] in registers
    float w0[NRBF], w1[NRBF], w2[NRBF], w3[NRBF];
    #pragma unroll
    for (int k = 0; k < NRBF; k++) {
        float4 wv = *(const float4*)&Wf[k * DB + lane * 4];
        w0[k] = wv.x; w1[k] = wv.y; w2[k] = wv.z; w3[k] = wv.w;
    }
    const float4 bv = *(const float4*)&bf[lane * 4];

    int p = gw;
    if (p >= N_PAIRS) return;

    // Prologue: metadata for first pair
    float fv = (lane < NRBF) ? __ldg(&f[(size_t)p * NRBF + lane]) : 0.f;
    int2  ij = g_pairs[p];
    float rc = __ldg(&rcut[p]);

    while (true) {
        // Issue the gather for the current pair immediately (latency hidden
        // under the Wij FMA chain below).
        float4 hv = *(const float4*)&g_h[(size_t)ij.y * DB + lane * 4];

        // Prefetch next pair's metadata.
        const int pn = p + nwarps;
        const bool more = pn < N_PAIRS;
        float fv_n = 0.f, rc_n = 0.f;
        int2  ij_n = make_int2(0, 0);
        if (more) {
            fv_n = (lane < NRBF) ? __ldg(&f[(size_t)pn * NRBF + lane]) : 0.f;
            ij_n = g_pairs[pn];
            rc_n = __ldg(&rcut[pn]);
        }

        // Wij for current pair
        float a0 = bv.x, a1 = bv.y, a2 = bv.z, a3 = bv.w;
        #pragma unroll
        for (int k = 0; k < NRBF; k++) {
            float fk = __shfl_sync(0xffffffffu, fv, k);
            a0 = fmaf(fk, w0[k], a0);
            a1 = fmaf(fk, w1[k], a1);
            a2 = fmaf(fk, w2[k], a2);
            a3 = fmaf(fk, w3[k], a3);
        }
        a0 = ssp(a0) * rc;
        a1 = ssp(a1) * rc;
        a2 = ssp(a2) * rc;
        a3 = ssp(a3) * rc;

        float4 v;
        v.x = hv.x * a0; v.y = hv.y * a1; v.z = hv.z * a2; v.w = hv.w * a3;
        red_add_v4(&g_agg[(size_t)ij.x * DB + lane * 4], v);

        if (!more) break;
        p = pn; fv = fv_n; ij = ij_n; rc = rc_n;
    }
}

// ----------------------------------------------------------------------------

extern "C" void kernel_launch(void* const* d_in, const int* in_sizes, int n_in,
                              void* d_out, int out_size)
{
    const float* x     = (const float*)d_in[0];
    const void*  pl    = d_in[1];
    const float* f_ij  = (const float*)d_in[2];
    const float* rcut  = (const float*)d_in[3];
    const float* W_in  = (const float*)d_in[4];
    const float* b_in  = (const float*)d_in[5];
    const float* W_f   = (const float*)d_in[6];
    const float* b_f   = (const float*)d_in[7];
    const float* W_out = (const float*)d_in[8];
    const float* b_out = (const float*)d_in[9];
    float*       out   = (float*)d_out;

    float* hbuf;  cudaGetSymbolAddress((void**)&hbuf, g_h);
    float* abuf;  cudaGetSymbolAddress((void**)&abuf, g_agg);

    const int gemm_grid = (N_ATOMS + 127) / 128;  // 391

    // 0) pairlist convert (with in-kernel dtype sniff)
    convert_idx_kernel<<<(N_PAIRS + 255) / 256, 256>>>(pl);
    // 1) agg = 0
    zero_agg_kernel<<<(N_ATOMS * DB / 4 + 255) / 256, 256>>>();
    // 2) h = x @ W_in + b_in
    gemm128_kernel<false><<<gemm_grid, 256>>>(x, W_in, b_in, hbuf, N_ATOMS);
    // 3) edges: gather/modulate/scatter (pipelined)
    edge_kernel<<<1776, 256>>>(f_ij, rcut, W_f, b_f);
    // 4) out = ssp(agg @ W_out + b_out)
    gemm128_kernel<true><<<gemm_grid, 256>>>(abuf, W_out, b_out, out, N_ATOMS);
}